// round 17
// baseline (speedup 1.0000x reference)
#include <cuda_runtime.h>
#include <cstdint>

#define MAXN   50000
#define MAXE   800000
#define F1     128
#define F2     64

// ---------------- static scratch ----------------
__device__ int   g_is64;
__device__ int   g_src   [MAXE];
__device__ int   g_dst   [MAXE];
__device__ int   g_cnt   [MAXN];
__device__ int   g_rowptr[MAXN + 1];
__device__ int   g_cur   [MAXN];
__device__ int   g_eidx  [MAXE];
__device__ float g_rdeg  [MAXN];
__device__ float g_agg1  [MAXN * F1];   // mean_{src->i} x[src]
__device__ float g_h     [MAXN * F1];   // relu([agg1|x] @ W1 + b1)
__device__ float g_p     [MAXN * F2];   // h @ W2_l
__device__ float g_q     [MAXN * F2];   // h @ W2_r

// ---------------- packed f32x2 helpers (base Blackwell family PTX) ----------------
#define FMA2(d, a, b, c) \
    asm("fma.rn.f32x2 %0, %1, %2, %3;" : "=l"(d) : "l"(a), "l"(b), "l"(c))
#define PACK2(d, s) \
    asm("mov.b64 %0, {%1, %1};" : "=l"(d) : "f"(s))
#define UNPK2(lo, hi, s) \
    asm("mov.b64 {%0, %1}, %2;" : "=f"(lo), "=f"(hi) : "l"(s))

// ============================================================
// CSR build
// ============================================================
__global__ void k_detect(const int* __restrict__ ei32) {
    if (threadIdx.x == 0 && blockIdx.x == 0) {
        int all0 = 1;
        for (int i = 1; i < 128; i += 2)
            if (ei32[i] != 0) { all0 = 0; break; }
        g_is64 = all0;
    }
}
__global__ __launch_bounds__(256)
void k_convert(const int* __restrict__ ei32, int E, int n) {
    int e = blockIdx.x * blockDim.x + threadIdx.x;
    if (e < n) g_cnt[e] = 0;
    if (e >= E) return;
    if (g_is64) { g_src[e] = ei32[2 * e]; g_dst[e] = ei32[2 * (E + e)]; }
    else        { g_src[e] = ei32[e];     g_dst[e] = ei32[E + e]; }
}
__global__ __launch_bounds__(256)
void k_hist(int E) {
    int e = blockIdx.x * blockDim.x + threadIdx.x;
    if (e >= E) return;
    int dst = g_dst[e];
    if ((unsigned)dst < (unsigned)MAXN) atomicAdd(&g_cnt[dst], 1);
}
// MLP-friendly single-block scan: thread-blocked chunks
__global__ __launch_bounds__(1024)
void k_scan(int n) {
    __shared__ int wsum[32];
    __shared__ int gtot;
    int tid = threadIdx.x, lane = tid & 31, wid = tid >> 5;
    int ch = (n + 1023) >> 10;
    int base = tid * ch;
    int s = 0;
#pragma unroll 8
    for (int i = 0; i < ch; i++) { int idx = base + i; if (idx < n) s += g_cnt[idx]; }
    int v = s;
#pragma unroll
    for (int o = 1; o < 32; o <<= 1) { int t = __shfl_up_sync(~0u, v, o); if (lane >= o) v += t; }
    if (lane == 31) wsum[wid] = v;
    __syncthreads();
    if (wid == 0) {
        int w = wsum[lane];
#pragma unroll
        for (int o = 1; o < 32; o <<= 1) { int t = __shfl_up_sync(~0u, w, o); if (lane >= o) w += t; }
        wsum[lane] = w;
        if (lane == 31) gtot = w;
    }
    __syncthreads();
    int run = (wid ? wsum[wid - 1] : 0) + (v - s);
    for (int i = 0; i < ch; i++) {
        int idx = base + i;
        if (idx < n) {
            int c = g_cnt[idx];
            g_rowptr[idx] = run; g_cur[idx] = run;
            g_rdeg[idx] = 1.0f / fmaxf((float)c, 1.0f);
            run += c;
        }
    }
    if (tid == 0) g_rowptr[n] = gtot;
}
__global__ __launch_bounds__(256)
void k_bin(int E) {
    int e = blockIdx.x * blockDim.x + threadIdx.x;
    if (e >= E) return;
    int src = g_src[e], dst = g_dst[e];
    if ((unsigned)dst >= (unsigned)MAXN) return;
    int pos = atomicAdd(&g_cur[dst], 1);
    if ((unsigned)pos < (unsigned)MAXE) g_eidx[pos] = src;
}

// ============================================================
// gather-aggregate layer 1: agg1[i] = rdeg[i] * sum x[src]
// ============================================================
__global__ __launch_bounds__(256)
void k_agg1(const float* __restrict__ x, int n) {
    int t = blockIdx.x * blockDim.x + threadIdx.x;
    int node = t >> 5;
    if (node >= n) return;
    int c = t & 31;
    int beg = g_rowptr[node], end = g_rowptr[node + 1];
    float4 s = make_float4(0.f, 0.f, 0.f, 0.f);
    const float4* x4 = reinterpret_cast<const float4*>(x);
    for (int e = beg; e < end; e++) {
        int src = g_eidx[e];
        float4 v = x4[(size_t)src * 32 + c];
        s.x += v.x; s.y += v.y; s.z += v.z; s.w += v.w;
    }
    float r = g_rdeg[node];
    s.x *= r; s.y *= r; s.z *= r; s.w *= r;
    reinterpret_cast<float4*>(g_agg1)[(size_t)node * 32 + c] = s;
}

// ============================================================
// GEMM1: h = relu([agg1 | x] @ [W1_l ; W1_r] + b1)
// M x 128, K = 256.  BM=128, BN=128, BK=16, 256 thr, 8x8/thr
// inner loop uses packed fma.rn.f32x2 (2 FMA per issue)
// ============================================================
__global__ __launch_bounds__(256)
void k_gemm1(const float* __restrict__ x,
             const float* __restrict__ W1l,
             const float* __restrict__ b1,
             const float* __restrict__ W1r, int M) {
    __shared__ float As[16][132];   // [k][m], padded
    __shared__ float Bs[16][128];   // [k][n]

    int tid  = threadIdx.x;
    int row0 = blockIdx.x * 128;

    unsigned long long acc2[8][4];  // 8 rows x 4 col-pairs, f32x2
#pragma unroll
    for (int i = 0; i < 8; i++)
#pragma unroll
        for (int j = 0; j < 4; j++) acc2[i][j] = 0ULL;

    int tr = tid >> 4;   // 0..15 row group
    int tc = tid & 15;   // 0..15 col group

    for (int kt = 0; kt < 16; kt++) {           // K = 256 in 16-chunks
        // ---- load A (512 float4 slots; 2 per thread) ----
#pragma unroll
        for (int l = 0; l < 2; l++) {
            int s  = tid * 2 + l;
            int r  = s >> 2;
            int kq = s & 3;
            int rg = row0 + r;
            int kg = kt * 16 + kq * 4;
            float4 v = make_float4(0.f, 0.f, 0.f, 0.f);
            if (rg < M) {
                if (kt < 8)
                    v = *reinterpret_cast<const float4*>(g_agg1 + (size_t)rg * F1 + kg);
                else
                    v = *reinterpret_cast<const float4*>(x + (size_t)rg * F1 + (kg - 128));
            }
            As[kq * 4 + 0][r] = v.x;
            As[kq * 4 + 1][r] = v.y;
            As[kq * 4 + 2][r] = v.z;
            As[kq * 4 + 3][r] = v.w;
        }
        // ---- load B (512 float4 slots; 2 per thread) ----
#pragma unroll
        for (int l = 0; l < 2; l++) {
            int s  = tid * 2 + l;
            int k  = s >> 5;
            int c4 = s & 31;
            int kg = kt * 16 + k;
            const float* Wsrc = (kt < 8) ? (W1l + kg * 128) : (W1r + (kg - 128) * 128);
            *reinterpret_cast<float4*>(&Bs[k][c4 * 4]) =
                *reinterpret_cast<const float4*>(Wsrc + c4 * 4);
        }
        __syncthreads();

#pragma unroll
        for (int k = 0; k < 16; k++) {
            float a[8];
            *reinterpret_cast<float4*>(a)     = *reinterpret_cast<const float4*>(&As[k][tr * 8]);
            *reinterpret_cast<float4*>(a + 4) = *reinterpret_cast<const float4*>(&As[k][tr * 8 + 4]);
            unsigned long long bb[4];
#pragma unroll
            for (int j = 0; j < 4; j++)
                bb[j] = *reinterpret_cast<const unsigned long long*>(&Bs[k][tc * 8 + 2 * j]);
#pragma unroll
            for (int i = 0; i < 8; i++) {
                unsigned long long aa;
                PACK2(aa, a[i]);
#pragma unroll
                for (int j = 0; j < 4; j++)
                    FMA2(acc2[i][j], aa, bb[j], acc2[i][j]);
            }
        }
        __syncthreads();
    }

    // epilogue: + bias, relu, store h
    float bb8[8];
#pragma unroll
    for (int j = 0; j < 8; j++) bb8[j] = b1[tc * 8 + j];
#pragma unroll
    for (int i = 0; i < 8; i++) {
        int rg = row0 + tr * 8 + i;
        if (rg >= M) continue;
        float o[8];
#pragma unroll
        for (int j = 0; j < 4; j++)
            UNPK2(o[2 * j], o[2 * j + 1], acc2[i][j]);
        float4 v0, v1;
        v0.x = fmaxf(o[0] + bb8[0], 0.f);
        v0.y = fmaxf(o[1] + bb8[1], 0.f);
        v0.z = fmaxf(o[2] + bb8[2], 0.f);
        v0.w = fmaxf(o[3] + bb8[3], 0.f);
        v1.x = fmaxf(o[4] + bb8[4], 0.f);
        v1.y = fmaxf(o[5] + bb8[5], 0.f);
        v1.z = fmaxf(o[6] + bb8[6], 0.f);
        v1.w = fmaxf(o[7] + bb8[7], 0.f);
        *reinterpret_cast<float4*>(g_h + (size_t)rg * F1 + tc * 8)     = v0;
        *reinterpret_cast<float4*>(g_h + (size_t)rg * F1 + tc * 8 + 4) = v1;
    }
}

// ============================================================
// GEMM2: [p | q] = h @ [W2_l | W2_r]   (M x 128, K = 128)
// ============================================================
__global__ __launch_bounds__(256)
void k_gemm2(const float* __restrict__ W2l,
             const float* __restrict__ W2r, int M) {
    __shared__ float As[16][132];
    __shared__ float Bs[16][128];

    int tid  = threadIdx.x;
    int row0 = blockIdx.x * 128;

    unsigned long long acc2[8][4];
#pragma unroll
    for (int i = 0; i < 8; i++)
#pragma unroll
        for (int j = 0; j < 4; j++) acc2[i][j] = 0ULL;

    int tr = tid >> 4;
    int tc = tid & 15;

    for (int kt = 0; kt < 8; kt++) {            // K = 128
#pragma unroll
        for (int l = 0; l < 2; l++) {
            int s  = tid * 2 + l;
            int r  = s >> 2;
            int kq = s & 3;
            int rg = row0 + r;
            int kg = kt * 16 + kq * 4;
            float4 v = make_float4(0.f, 0.f, 0.f, 0.f);
            if (rg < M)
                v = *reinterpret_cast<const float4*>(g_h + (size_t)rg * F1 + kg);
            As[kq * 4 + 0][r] = v.x;
            As[kq * 4 + 1][r] = v.y;
            As[kq * 4 + 2][r] = v.z;
            As[kq * 4 + 3][r] = v.w;
        }
#pragma unroll
        for (int l = 0; l < 2; l++) {
            int s   = tid * 2 + l;
            int k   = s >> 5;
            int c4  = s & 31;
            int kg  = kt * 16 + k;
            int col = c4 * 4;
            const float* Wsrc = (col < 64) ? (W2l + kg * 64 + col)
                                           : (W2r + kg * 64 + (col - 64));
            *reinterpret_cast<float4*>(&Bs[k][col]) =
                *reinterpret_cast<const float4*>(Wsrc);
        }
        __syncthreads();

#pragma unroll
        for (int k = 0; k < 16; k++) {
            float a[8];
            *reinterpret_cast<float4*>(a)     = *reinterpret_cast<const float4*>(&As[k][tr * 8]);
            *reinterpret_cast<float4*>(a + 4) = *reinterpret_cast<const float4*>(&As[k][tr * 8 + 4]);
            unsigned long long bb[4];
#pragma unroll
            for (int j = 0; j < 4; j++)
                bb[j] = *reinterpret_cast<const unsigned long long*>(&Bs[k][tc * 8 + 2 * j]);
#pragma unroll
            for (int i = 0; i < 8; i++) {
                unsigned long long aa;
                PACK2(aa, a[i]);
#pragma unroll
                for (int j = 0; j < 4; j++)
                    FMA2(acc2[i][j], aa, bb[j], acc2[i][j]);
            }
        }
        __syncthreads();
    }

    // cols [0,64) -> p ; cols [64,128) -> q (split lands exactly at tc==8)
    float* dst = (tc < 8) ? g_p : g_q;
    int    cb  = (tc < 8) ? tc * 8 : tc * 8 - 64;
#pragma unroll
    for (int i = 0; i < 8; i++) {
        int rg = row0 + tr * 8 + i;
        if (rg >= M) continue;
        float o[8];
#pragma unroll
        for (int j = 0; j < 4; j++)
            UNPK2(o[2 * j], o[2 * j + 1], acc2[i][j]);
        float4 v0, v1;
        v0.x = o[0]; v0.y = o[1]; v0.z = o[2]; v0.w = o[3];
        v1.x = o[4]; v1.y = o[5]; v1.z = o[6]; v1.w = o[7];
        *reinterpret_cast<float4*>(dst + (size_t)rg * F2 + cb)     = v0;
        *reinterpret_cast<float4*>(dst + (size_t)rg * F2 + cb + 4) = v1;
    }
}

// ============================================================
// gather layer 2 + epilogue: out = rdeg*sum p[src] + b2 + q
// ============================================================
__global__ __launch_bounds__(256)
void k_aggfinal(const float* __restrict__ b2, float* __restrict__ out, int n) {
    int t = blockIdx.x * blockDim.x + threadIdx.x;
    int node = t >> 4;
    if (node >= n) return;
    int c = t & 15;
    int beg = g_rowptr[node], end = g_rowptr[node + 1];
    float4 s = make_float4(0.f, 0.f, 0.f, 0.f);
    const float4* p4 = reinterpret_cast<const float4*>(g_p);
    for (int e = beg; e < end; e++) {
        int src = g_eidx[e];
        float4 v = p4[(size_t)src * 16 + c];
        s.x += v.x; s.y += v.y; s.z += v.z; s.w += v.w;
    }
    float  r = g_rdeg[node];
    float4 q = reinterpret_cast<const float4*>(g_q)[(size_t)node * 16 + c];
    float4 b = reinterpret_cast<const float4*>(b2)[c];
    float4 o;
    o.x = s.x * r + b.x + q.x;
    o.y = s.y * r + b.y + q.y;
    o.z = s.z * r + b.z + q.z;
    o.w = s.w * r + b.w + q.w;
    reinterpret_cast<float4*>(out)[(size_t)node * 16 + c] = o;
}

// ============================================================
extern "C" void kernel_launch(void* const* d_in, const int* in_sizes, int n_in,
                              void* d_out, int out_size) {
    const float* x    = (const float*)d_in[0];
    const int*   ei32 = (const int*)d_in[1];
    const float* W1l  = (const float*)d_in[2];
    const float* b1   = (const float*)d_in[3];
    const float* W1r  = (const float*)d_in[4];
    const float* W2l  = (const float*)d_in[5];
    const float* b2   = (const float*)d_in[6];
    const float* W2r  = (const float*)d_in[7];
    float*       out  = (float*)d_out;

    int N = in_sizes[0] / F1;          // 50000
    int E = in_sizes[1] / 2;           // 800000

    k_detect <<<1, 32>>>(ei32);
    {
        int tot = (E > N) ? E : N;
        k_convert<<<(tot + 255) / 256, 256>>>(ei32, E, N);
    }
    k_hist<<<(E + 255) / 256, 256>>>(E);
    k_scan<<<1, 1024>>>(N);
    k_bin <<<(E + 255) / 256, 256>>>(E);

    k_agg1 <<<(N * 32 + 255) / 256, 256>>>(x, N);
    k_gemm1<<<(N + 127) / 128, 256>>>(x, W1l, b1, W1r, N);

    k_gemm2   <<<(N + 127) / 128, 256>>>(W2l, W2r, N);
    k_aggfinal<<<(N * 16 + 255) / 256, 256>>>(b2, out, N);
}